// round 5
// baseline (speedup 1.0000x reference)
#include <cuda_runtime.h>
#include <cuda_bf16.h>
#include <cstdint>

// ---------------- problem constants ----------------
#define B_TOTAL 262144
#define D 64
#define K 1024
#define M_CTA 256
#define NT 256
#define QSCALE 2032.0f
#define S2     (1.0f / (QSCALE * QSCALE))
#define S2_128 (128.0f * S2)
#define TH     0.02f

// Output layout (float32, reference return order)
#define OFF_ZQ    0
#define OFF_IDX   16777216            // B*D
#define OFF_LOSS  17039360            // + B
#define OFF_CS    17039361            // + 1
#define OFF_ES    17040385            // + K
#define OFF_W     17105921            // + K*D

// ---------------- device scratch ----------------
__device__ float          g_wsq[K];      // -0.5*||w||^2
__device__ unsigned int   g_counts[K];
__device__ float          g_embed[K * D];
__device__ float          g_loss;
__device__ float          g_n;
__device__ int8_t         g_w8h[K * D];
__device__ int8_t         g_w8l[K * D];

// ---------------- smem layout (dynamic, bytes) ----------------
// tiles: buf{0,1} x plane{hi,lo} x (128 rows x 80B)
#define SMT_BUF(b)   ((b) * 20480)
#define SMT_PLANE(p) ((p) * 10240)
#define SM_W2   40960
#define SM_HIST 45056
#define SM_CI   49152     // int2 [256][4]
#define SM_CS   57344     // float2 [256][4]
#define SM_TOTAL 65536

__device__ __forceinline__ void red_add_v4(float* p, float4 v) {
    asm volatile("red.global.add.v4.f32 [%0], {%1,%2,%3,%4};"
                 :: "l"(p), "f"(v.x), "f"(v.y), "f"(v.z), "f"(v.w) : "memory");
}

__device__ __forceinline__ void mma8(int c[4], const uint32_t a[4],
                                     uint32_t b0, uint32_t b1) {
    asm volatile("mma.sync.aligned.m16n8k32.row.col.s32.s8.s8.s32 "
                 "{%0,%1,%2,%3}, {%4,%5,%6,%7}, {%8,%9}, {%0,%1,%2,%3};"
                 : "+r"(c[0]), "+r"(c[1]), "+r"(c[2]), "+r"(c[3])
                 : "r"(a[0]), "r"(a[1]), "r"(a[2]), "r"(a[3]), "r"(b0), "r"(b1));
}

__device__ __forceinline__ void ldmx4(uint32_t r[4], uint32_t saddr) {
    asm volatile("ldmatrix.sync.aligned.m8n8.x4.shared.b16 {%0,%1,%2,%3}, [%4];"
                 : "=r"(r[0]), "=r"(r[1]), "=r"(r[2]), "=r"(r[3]) : "r"(saddr));
}

__device__ __forceinline__ void cpasync16(uint32_t dst, const void* src) {
    asm volatile("cp.async.ca.shared.global [%0], [%1], 16;"
                 :: "r"(dst), "l"(src) : "memory");
}

__device__ __forceinline__ void quant8(float x, int& hi, int& lo) {
    int q = __float2int_rn(x * QSCALE);
    q = max(min(q, 16256), -16256);
    lo = ((q + 64) & 127) - 64;
    hi = (q - lo) >> 7;
}
__device__ __forceinline__ uint32_t pack4(int a, int b, int c, int d) {
    return (uint32_t)(a & 255) | ((uint32_t)(b & 255) << 8) |
           ((uint32_t)(c & 255) << 16) | ((uint32_t)(d & 255) << 24);
}

// ---------------- zero scratch ----------------
__global__ void vq_zero() {
    int i = blockIdx.x * blockDim.x + threadIdx.x;
    if (i < K * D) g_embed[i] = 0.0f;
    if (i < K)     g_counts[i] = 0u;
    if (i == 0)    g_loss = 0.0f;
}

// ---------------- prep: quantize codebook to int8 digits + (-0.5 w2) ----------------
__global__ void vq_prep8(const float* __restrict__ weight) {
    int k = blockIdx.x * blockDim.x + threadIdx.x;
    if (k >= K) return;
    const float4* wp = (const float4*)(weight + (size_t)k * D);
    float s = 0.0f;
    uint32_t H[16], L[16];
#pragma unroll
    for (int j = 0; j < 16; j++) {
        float4 v = wp[j];
        s = fmaf(v.x, v.x, s); s = fmaf(v.y, v.y, s);
        s = fmaf(v.z, v.z, s); s = fmaf(v.w, v.w, s);
        int h0, l0, h1, l1, h2, l2, h3, l3;
        quant8(v.x, h0, l0); quant8(v.y, h1, l1);
        quant8(v.z, h2, l2); quant8(v.w, h3, l3);
        H[j] = pack4(h0, h1, h2, h3);
        L[j] = pack4(l0, l1, l2, l3);
    }
    uint4* dh = (uint4*)(g_w8h + (size_t)k * D);
    uint4* dl = (uint4*)(g_w8l + (size_t)k * D);
#pragma unroll
    for (int i = 0; i < 4; i++) {
        dh[i] = make_uint4(H[4*i], H[4*i+1], H[4*i+2], H[4*i+3]);
        dl[i] = make_uint4(L[4*i], L[4*i+1], L[4*i+2], L[4*i+3]);
    }
    g_wsq[k] = -0.5f * s;
}

// ---------------- main fused kernel ----------------
__global__ __launch_bounds__(NT, 2)
void vq_main(const float* __restrict__ z,
             const float* __restrict__ weight,
             float* __restrict__ out_zq,
             float* __restrict__ out_idx) {
    extern __shared__ char sm[];
    const uint32_t smu = (uint32_t)__cvta_generic_to_shared(sm);
    const int tid  = threadIdx.x;
    const int wid  = tid >> 5;
    const int lane = tid & 31;
    const int wrb  = wid * 32;
    const int row0 = blockIdx.x * M_CTA;

    float*        sW2n  = (float*)(sm + SM_W2);
    unsigned int* sHist = (unsigned int*)(sm + SM_HIST);
    int2*         sCI   = (int2*)(sm + SM_CI);
    float2*       sCS   = (float2*)(sm + SM_CS);

    for (int i = tid; i < K; i += NT) { sW2n[i] = g_wsq[i]; sHist[i] = 0u; }

    // prefetch codebook tile 0 -> buf0
    {
        const int r = tid >> 1, p = tid & 1;
        const int8_t* src = (p ? g_w8l : g_w8h) + (size_t)r * 64;
        uint32_t dst = smu + SMT_BUF(0) + SMT_PLANE(p) + r * 80;
#pragma unroll
        for (int j = 0; j < 4; j++) cpasync16(dst + j * 16, src + j * 16);
        asm volatile("cp.async.commit_group;" ::: "memory");
    }

    // ---- phase 1: stage z (2 halves) into buf1, build A fragments ----
    uint32_t aH[2][2][4], aL[2][2][4];
#pragma unroll 1
    for (int h = 0; h < 2; h++) {
        __syncthreads();
        {
            const int sr = tid >> 1, scq = (tid & 1) * 32;   // 32 elems each
            const float4* zp = (const float4*)(z + ((size_t)(row0 + h * 128 + sr)) * D + scq);
            uint32_t Hq[8], Lq[8];
#pragma unroll
            for (int j = 0; j < 8; j++) {
                float4 v = zp[j];
                int h0, l0, h1, l1, h2, l2, h3, l3;
                quant8(v.x, h0, l0); quant8(v.y, h1, l1);
                quant8(v.z, h2, l2); quant8(v.w, h3, l3);
                Hq[j] = pack4(h0, h1, h2, h3);
                Lq[j] = pack4(l0, l1, l2, l3);
            }
            uint4* dH = (uint4*)(sm + SMT_BUF(1) + SMT_PLANE(0) + sr * 80 + scq);
            uint4* dL = (uint4*)(sm + SMT_BUF(1) + SMT_PLANE(1) + sr * 80 + scq);
            dH[0] = make_uint4(Hq[0], Hq[1], Hq[2], Hq[3]);
            dH[1] = make_uint4(Hq[4], Hq[5], Hq[6], Hq[7]);
            dL[0] = make_uint4(Lq[0], Lq[1], Lq[2], Lq[3]);
            dL[1] = make_uint4(Lq[4], Lq[5], Lq[6], Lq[7]);
        }
        __syncthreads();
        if ((wid >> 2) == h) {
            const int mbase = (wid & 3) * 32;
            const int rowoff = (mbase + (lane & 7) + (((lane >> 3) & 1) ? 8 : 0)) * 80
                             + ((lane >> 4) ? 16 : 0);
#pragma unroll
            for (int f = 0; f < 2; f++)
#pragma unroll
            for (int c = 0; c < 2; c++) {
                uint32_t ad = smu + SMT_BUF(1) + rowoff + f * 16 * 80 + c * 32;
                ldmx4(aH[f][c], ad + SMT_PLANE(0));
                ldmx4(aL[f][c], ad + SMT_PLANE(1));
            }
        }
    }

    // ---- phase 2: stream codebook tiles, s8 MMA, per-lane top-2 ----
    float tb[4], tb2[4];
    int   ti[4], ti2[4];
#pragma unroll
    for (int s = 0; s < 4; s++) { tb[s] = -3.4e38f; tb2[s] = -3.4e38f; ti[s] = 0; ti2[s] = 0; }

    const uint32_t lmB = (uint32_t)((lane & 7) * 80 + (lane >> 3) * 16);

#pragma unroll 1
    for (int t = 0; t < 8; t++) {
        __syncthreads();    // prior compute on buf[(t+1)&1] done; safe to overwrite
        if (t < 7) {
            const int r = tid >> 1, p = tid & 1;
            const int8_t* src = (p ? g_w8l : g_w8h) + ((size_t)(t + 1) * 128 + r) * 64;
            uint32_t dst = smu + SMT_BUF((t + 1) & 1) + SMT_PLANE(p) + r * 80;
#pragma unroll
            for (int j = 0; j < 4; j++) cpasync16(dst + j * 16, src + j * 16);
            asm volatile("cp.async.commit_group;" ::: "memory");
            asm volatile("cp.async.wait_group 1;" ::: "memory");
        } else {
            asm volatile("cp.async.wait_group 0;" ::: "memory");
        }
        __syncthreads();

        const uint32_t tb_hi = smu + SMT_BUF(t & 1);
#pragma unroll 1
        for (int nb = 0; nb < 16; nb++) {
            uint32_t bh[4], bl[4];
            uint32_t ba = tb_hi + (uint32_t)nb * 640u + lmB;
            ldmx4(bh, ba);
            ldmx4(bl, ba + 10240);

            int cHH[2][4], cM[2][4], cLL[2][4];
#pragma unroll
            for (int f = 0; f < 2; f++)
#pragma unroll
            for (int e = 0; e < 4; e++) { cHH[f][e] = 0; cM[f][e] = 0; cLL[f][e] = 0; }

#pragma unroll
            for (int c = 0; c < 2; c++) {
                mma8(cHH[0], aH[0][c], bh[2*c], bh[2*c+1]);
                mma8(cHH[1], aH[1][c], bh[2*c], bh[2*c+1]);
                mma8(cM[0],  aH[0][c], bl[2*c], bl[2*c+1]);
                mma8(cM[1],  aH[1][c], bl[2*c], bl[2*c+1]);
                mma8(cM[0],  aL[0][c], bh[2*c], bh[2*c+1]);
                mma8(cM[1],  aL[1][c], bh[2*c], bh[2*c+1]);
                mma8(cLL[0], aL[0][c], bl[2*c], bl[2*c+1]);
                mma8(cLL[1], aL[1][c], bl[2*c], bl[2*c+1]);
            }

            const int colb = t * 128 + nb * 8 + (lane & 3) * 2;
            float2 w2 = *(const float2*)&sW2n[colb];

#define UPD(s, v, ix) do {                                                     \
                float _v = (v); int _ix = (ix);                                \
                if (_v > tb[s]) { tb2[s]=tb[s]; ti2[s]=ti[s]; tb[s]=_v; ti[s]=_ix; } \
                else if (_v > tb2[s]) { tb2[s]=_v; ti2[s]=_ix; }               \
            } while (0)
#pragma unroll
            for (int f = 0; f < 2; f++) {
                int m0 = cHH[f][0] * 128 + cM[f][0];
                int m1 = cHH[f][1] * 128 + cM[f][1];
                int m2 = cHH[f][2] * 128 + cM[f][2];
                int m3 = cHH[f][3] * 128 + cM[f][3];
                float v0 = fmaf((float)m0, S2_128, fmaf((float)cLL[f][0], S2, w2.x));
                float v1 = fmaf((float)m1, S2_128, fmaf((float)cLL[f][1], S2, w2.y));
                float v2 = fmaf((float)m2, S2_128, fmaf((float)cLL[f][2], S2, w2.x));
                float v3 = fmaf((float)m3, S2_128, fmaf((float)cLL[f][3], S2, w2.y));
                UPD(2*f,   v0, colb);  UPD(2*f,   v1, colb + 1);
                UPD(2*f+1, v2, colb);  UPD(2*f+1, v3, colb + 1);
            }
#undef UPD
        }
    }

    // ---- write per-lane candidates (no cross-lane merge; 8 cands/row) ----
#pragma unroll
    for (int s = 0; s < 4; s++) {
        int rl = wrb + (lane >> 2) + 8 * s;
        sCI[rl * 4 + (lane & 3)] = make_int2(ti[s], ti2[s]);
        sCS[rl * 4 + (lane & 3)] = make_float2(tb[s], tb2[s]);
    }
    __syncthreads();

    // ---- epilogue: exact fp32 re-check of candidates near the approx best ----
    {
        const int row = row0 + tid;
        float sc[8]; int id[8];
#pragma unroll
        for (int q = 0; q < 4; q++) {
            int2   ci = sCI[tid * 4 + q];
            float2 cs = sCS[tid * 4 + q];
            sc[2*q] = cs.x; id[2*q] = ci.x;
            sc[2*q+1] = cs.y; id[2*q+1] = ci.y;
        }
        float bs = sc[0];
#pragma unroll
        for (int q = 1; q < 8; q++) bs = fmaxf(bs, sc[q]);

        float4 zr[D / 4];
        const float4* zp = (const float4*)(z + (size_t)row * D);
#pragma unroll
        for (int j = 0; j < D / 4; j++) zr[j] = zp[j];

        float bd2 = 3.4e38f; int bidx = K;
#pragma unroll 1
        for (int q = 0; q < 8; q++) {
            if (sc[q] >= bs - TH) {
                const float4* wv = (const float4*)(weight + (size_t)id[q] * D);
                float d2 = 0.0f;
#pragma unroll
                for (int j = 0; j < D / 4; j++) {
                    float4 w = wv[j];
                    float dx = zr[j].x - w.x, dy = zr[j].y - w.y;
                    float dz = zr[j].z - w.z, dw = zr[j].w - w.w;
                    d2 = fmaf(dx, dx, d2); d2 = fmaf(dy, dy, d2);
                    d2 = fmaf(dz, dz, d2); d2 = fmaf(dw, dw, d2);
                }
                if (d2 < bd2 || (d2 == bd2 && id[q] < bidx)) { bd2 = d2; bidx = id[q]; }
            }
        }

        const float4* wv = (const float4*)(weight + (size_t)bidx * D);
        float4* op = (float4*)(out_zq + (size_t)row * D);
        float* eb = g_embed + (size_t)bidx * D;
#pragma unroll
        for (int j = 0; j < D / 4; j++) {
            op[j] = wv[j];
            red_add_v4(eb + 4 * j, zr[j]);
        }
        out_idx[row] = (float)bidx;
        atomicAdd(&sHist[bidx], 1u);

        float d2 = bd2;
#pragma unroll
        for (int o = 16; o; o >>= 1) d2 += __shfl_xor_sync(0xffffffffu, d2, o);
        if (lane == 0) atomicAdd(&g_loss, d2);
    }
    __syncthreads();
    for (int i = tid; i < K; i += NT) {
        unsigned int c = sHist[i];
        if (c) atomicAdd(&g_counts[i], c);
    }
}

// ---------------- finalize ----------------
__global__ void vq_finalA(const float* __restrict__ ema_cs, float* __restrict__ out) {
    __shared__ float sSum[K];
    int k = threadIdx.x;
    float ncs = fmaf(0.99f, ema_cs[k], 0.01f * (float)g_counts[k]);
    out[OFF_CS + k] = ncs;
    sSum[k] = ncs;
    __syncthreads();
#pragma unroll
    for (int s = K / 2; s > 0; s >>= 1) {
        if (k < s) sSum[k] += sSum[k + s];
        __syncthreads();
    }
    if (k == 0) {
        g_n = sSum[0];
        out[OFF_LOSS] = 0.25f * g_loss / (float)(B_TOTAL * D);
    }
}

__global__ void vq_finalB(const float* __restrict__ ema_es,
                          const float* __restrict__ ema_cs,
                          float* __restrict__ out) {
    int i = blockIdx.x * blockDim.x + threadIdx.x;
    if (i >= K * D) return;
    int k = i >> 6;
    float nes = fmaf(0.99f, ema_es[i], 0.01f * g_embed[i]);
    out[OFF_ES + i] = nes;
    float ncs = fmaf(0.99f, ema_cs[k], 0.01f * (float)g_counts[k]);
    float n = g_n;
    float smoothed = (ncs + 1e-5f) / (n + (float)K * 1e-5f) * n;
    out[OFF_W + i] = nes / smoothed;
}

extern "C" void kernel_launch(void* const* d_in, const int* in_sizes, int n_in,
                              void* d_out, int out_size) {
    const float* z      = (const float*)d_in[0];
    const float* weight = (const float*)d_in[1];
    const float* ema_cs = (const float*)d_in[2];
    const float* ema_es = (const float*)d_in[3];
    float* out = (float*)d_out;

    cudaFuncSetAttribute(vq_main, cudaFuncAttributeMaxDynamicSharedMemorySize, SM_TOTAL);

    vq_zero<<<(K * D + 255) / 256, 256>>>();
    vq_prep8<<<(K + 255) / 256, 256>>>(weight);
    vq_main<<<B_TOTAL / M_CTA, NT, SM_TOTAL>>>(z, weight, out + OFF_ZQ, out + OFF_IDX);
    vq_finalA<<<1, K>>>(ema_cs, out);
    vq_finalB<<<(K * D + 255) / 256, 256>>>(ema_es, ema_cs, out);
}

// round 6
// speedup vs baseline: 2.4906x; 2.4906x over previous
#include <cuda_runtime.h>
#include <cuda_bf16.h>
#include <cstdint>

// ---------------- problem constants ----------------
#define B_TOTAL 262144
#define D 64
#define K 1024
#define M_CTA 256            // rows per CTA
#define NT 256               // threads per CTA
#define TH 0.15f

// Output layout (float32, reference return order)
#define OFF_ZQ    0
#define OFF_IDX   16777216            // B*D
#define OFF_LOSS  17039360            // + B
#define OFF_CS    17039361            // + 1
#define OFF_ES    17040385            // + K
#define OFF_W     17105921            // + K*D

// ---------------- device scratch (no cudaMalloc allowed) ----------------
__device__ float          g_wsq[K];      // -0.5*||w||^2
__device__ unsigned int   g_counts[K];
__device__ float          g_embed[K * D];
__device__ float          g_loss;
__device__ float          g_n;
__device__ __nv_bfloat16  g_wh[K * D];

// ---------------- dynamic smem layout (bytes) ----------------
#define SM_SH   0          // 128 rows x 144B  (z hi staging / codebook hi tiles)
#define SM_SL   18432      // 128 rows x 144B  (z lo staging)
#define SM_W2   36864      // 1024 f32
#define SM_HIST 40960      // 1024 u32
#define SM_CI   45056      // int2 [256][4]
#define SM_CS   53248      // float2 [256][4]
#define SM_TOTAL 61440

__device__ __forceinline__ void red_add_v4(float* p, float4 v) {
    asm volatile("red.global.add.v4.f32 [%0], {%1,%2,%3,%4};"
                 :: "l"(p), "f"(v.x), "f"(v.y), "f"(v.z), "f"(v.w) : "memory");
}

__device__ __forceinline__ void mma16816(float c[4], const uint32_t a[4],
                                         uint32_t b0, uint32_t b1) {
    asm volatile("mma.sync.aligned.m16n8k16.row.col.f32.bf16.bf16.f32 "
                 "{%0,%1,%2,%3}, {%4,%5,%6,%7}, {%8,%9}, {%0,%1,%2,%3};"
                 : "+f"(c[0]), "+f"(c[1]), "+f"(c[2]), "+f"(c[3])
                 : "r"(a[0]), "r"(a[1]), "r"(a[2]), "r"(a[3]), "r"(b0), "r"(b1));
}

__device__ __forceinline__ void ldmx4(uint32_t r[4], uint32_t saddr) {
    asm volatile("ldmatrix.sync.aligned.m8n8.x4.shared.b16 {%0,%1,%2,%3}, [%4];"
                 : "=r"(r[0]), "=r"(r[1]), "=r"(r[2]), "=r"(r[3]) : "r"(saddr));
}

// ---------------- zero scratch ----------------
__global__ void vq_zero() {
    int i = blockIdx.x * blockDim.x + threadIdx.x;
    if (i < K * D) g_embed[i] = 0.0f;
    if (i < K)     g_counts[i] = 0u;
    if (i == 0)    g_loss = 0.0f;
}

// ---------------- prep: bf16 codebook + (-0.5*w2) ----------------
__global__ void vq_prep(const float* __restrict__ weight) {
    int k = blockIdx.x * blockDim.x + threadIdx.x;
    if (k >= K) return;
    const float4* wp = (const float4*)(weight + (size_t)k * D);
    float s = 0.0f;
    for (int j = 0; j < D / 4; j++) {
        float4 v = wp[j];
        s = fmaf(v.x, v.x, s); s = fmaf(v.y, v.y, s);
        s = fmaf(v.z, v.z, s); s = fmaf(v.w, v.w, s);
        __nv_bfloat162 p0 = __floats2bfloat162_rn(v.x, v.y);
        __nv_bfloat162 p1 = __floats2bfloat162_rn(v.z, v.w);
        uint2 H = make_uint2(*(uint32_t*)&p0, *(uint32_t*)&p1);
        ((uint2*)(g_wh + (size_t)k * D))[j] = H;
    }
    g_wsq[k] = -0.5f * s;
}

// ---------------- main fused kernel ----------------
__global__ __launch_bounds__(NT, 2)
void vq_main(const float* __restrict__ z,
             const float* __restrict__ weight,
             float* __restrict__ out_zq,
             float* __restrict__ out_idx) {
    extern __shared__ char sm[];
    const uint32_t smu = (uint32_t)__cvta_generic_to_shared(sm);
    const int tid  = threadIdx.x;
    const int wid  = tid >> 5;
    const int lane = tid & 31;
    const int wrb  = wid * 32;
    const int row0 = blockIdx.x * M_CTA;

    char*         sH    = sm + SM_SH;
    char*         sL    = sm + SM_SL;
    float*        sW2n  = (float*)(sm + SM_W2);
    unsigned int* sHist = (unsigned int*)(sm + SM_HIST);
    int2*         sCI   = (int2*)(sm + SM_CI);
    float2*       sCS   = (float2*)(sm + SM_CS);

    for (int i = tid; i < K; i += NT) { sW2n[i] = g_wsq[i]; sHist[i] = 0u; }

    // ---- phase 1: stage z (two halves of 128 rows), build A fragments ----
    uint32_t aH[2][4][4], aL[2][4][4];
    const int sr = tid >> 1;
    const int sc = (tid & 1) * 32;
#pragma unroll 1
    for (int h = 0; h < 2; h++) {
        __syncthreads();
        {
            const float4* zp = (const float4*)(z + ((size_t)(row0 + h * 128 + sr)) * D + sc);
            uint2* dH = (uint2*)(sH + sr * 144 + sc * 2);
            uint2* dL = (uint2*)(sL + sr * 144 + sc * 2);
#pragma unroll
            for (int j = 0; j < 8; j++) {
                float4 v = zp[j];
                float f[4] = {v.x, v.y, v.z, v.w};
                unsigned short hh[4], ll[4];
#pragma unroll
                for (int e = 0; e < 4; e++) {
                    __nv_bfloat16 bh = __float2bfloat16_rn(f[e]);
                    float fh = __bfloat162float(bh);
                    __nv_bfloat16 bl = __float2bfloat16_rn(f[e] - fh);
                    hh[e] = __bfloat16_as_ushort(bh);
                    ll[e] = __bfloat16_as_ushort(bl);
                }
                uint2 H, L;
                H.x = (uint32_t)hh[0] | ((uint32_t)hh[1] << 16);
                H.y = (uint32_t)hh[2] | ((uint32_t)hh[3] << 16);
                L.x = (uint32_t)ll[0] | ((uint32_t)ll[1] << 16);
                L.y = (uint32_t)ll[2] | ((uint32_t)ll[3] << 16);
                dH[j] = H; dL[j] = L;
            }
        }
        __syncthreads();
        if ((wid >> 2) == h) {
            const int br = (wid & 3) * 32;
#pragma unroll
            for (int f = 0; f < 2; f++)
#pragma unroll
            for (int kk = 0; kk < 4; kk++) {
                int rr = br + f * 16 + (lane >> 2);
                int cb = (kk * 16 + (lane & 3) * 2) * 2;
                aH[f][kk][0] = *(const uint32_t*)(sH + rr * 144 + cb);
                aH[f][kk][1] = *(const uint32_t*)(sH + (rr + 8) * 144 + cb);
                aH[f][kk][2] = *(const uint32_t*)(sH + rr * 144 + cb + 16);
                aH[f][kk][3] = *(const uint32_t*)(sH + (rr + 8) * 144 + cb + 16);
                aL[f][kk][0] = *(const uint32_t*)(sL + rr * 144 + cb);
                aL[f][kk][1] = *(const uint32_t*)(sL + (rr + 8) * 144 + cb);
                aL[f][kk][2] = *(const uint32_t*)(sL + rr * 144 + cb + 16);
                aL[f][kk][3] = *(const uint32_t*)(sL + (rr + 8) * 144 + cb + 16);
            }
        }
    }

    // ldmatrix B addressing (validated in R4)
    const uint32_t lmB = (uint32_t)((lane & 7) * 144 + (lane >> 3) * 16);
    const uint32_t sH_u = smu + SM_SH;

    // ---- phase 2: stream codebook hi tiles, HMMA (2 passes), per-lane top-2 ----
    float tb[4], tb2[4];
    int   ti[4], ti2[4];
#pragma unroll
    for (int s = 0; s < 4; s++) { tb[s] = -3.4e38f; tb2[s] = -3.4e38f; ti[s] = 0; ti2[s] = 0; }

#pragma unroll 1
    for (int t = 0; t < K / 128; t++) {
        __syncthreads();
        {
            // hi plane only: 128 rows x 128B; each thread 64B
            const uint4* gh = (const uint4*)(g_wh + ((size_t)(t * 128 + sr)) * D + sc);
            uint4* dh = (uint4*)(sH + sr * 144 + sc * 2);
#pragma unroll
            for (int j = 0; j < 4; j++) dh[j] = gh[j];
        }
        __syncthreads();

#pragma unroll 1
        for (int nb = 0; nb < 16; nb++) {
            const int colb = t * 128 + nb * 8 + (lane & 3) * 2;
            float2 w2 = *(const float2*)&sW2n[colb];

            uint32_t bh[8];
            {
                uint32_t base = (uint32_t)(nb * 8) * 144u + lmB;
                ldmx4(bh,     sH_u + base);
                ldmx4(bh + 4, sH_u + base + 64);
            }

            float cA0[4] = {w2.x, w2.y, w2.x, w2.y};
            float cA1[4] = {w2.x, w2.y, w2.x, w2.y};
            float cB0[4] = {0.f, 0.f, 0.f, 0.f};
            float cB1[4] = {0.f, 0.f, 0.f, 0.f};

#pragma unroll
            for (int kk = 0; kk < 4; kk++) {
                float* t0 = (kk & 1) ? cB0 : cA0;
                float* t1 = (kk & 1) ? cB1 : cA1;
                mma16816(t0, aH[0][kk], bh[2 * kk], bh[2 * kk + 1]);
                mma16816(t1, aH[1][kk], bh[2 * kk], bh[2 * kk + 1]);
            }
#pragma unroll
            for (int kk = 0; kk < 4; kk++) {
                float* t0 = (kk & 1) ? cB0 : cA0;
                float* t1 = (kk & 1) ? cB1 : cA1;
                mma16816(t0, aL[0][kk], bh[2 * kk], bh[2 * kk + 1]);
                mma16816(t1, aL[1][kk], bh[2 * kk], bh[2 * kk + 1]);
            }

            float c0f[4] = {cA0[0] + cB0[0], cA0[1] + cB0[1], cA0[2] + cB0[2], cA0[3] + cB0[3]};
            float c1f[4] = {cA1[0] + cB1[0], cA1[1] + cB1[1], cA1[2] + cB1[2], cA1[3] + cB1[3]};

#define UPD(s, v, ix) do {                                                     \
                float _v = (v); int _ix = (ix);                                \
                if (_v > tb[s]) { tb2[s]=tb[s]; ti2[s]=ti[s]; tb[s]=_v; ti[s]=_ix; } \
                else if (_v > tb2[s]) { tb2[s]=_v; ti2[s]=_ix; }               \
            } while (0)
            UPD(0, c0f[0], colb);  UPD(0, c0f[1], colb + 1);
            UPD(1, c0f[2], colb);  UPD(1, c0f[3], colb + 1);
            UPD(2, c1f[0], colb);  UPD(2, c1f[1], colb + 1);
            UPD(3, c1f[2], colb);  UPD(3, c1f[3], colb + 1);
#undef UPD
        }
    }

    // ---- write per-lane candidates (8 per row) ----
#pragma unroll
    for (int s = 0; s < 4; s++) {
        int rl = wrb + (lane >> 2) + 8 * s;
        sCI[rl * 4 + (lane & 3)] = make_int2(ti[s], ti2[s]);
        sCS[rl * 4 + (lane & 3)] = make_float2(tb[s], tb2[s]);
    }
    __syncthreads();

    // ---- epilogue: exact fp32 re-check of candidates near the approx best ----
    {
        const int row = row0 + tid;
        float scv[8]; int idv[8];
#pragma unroll
        for (int q = 0; q < 4; q++) {
            int2   ci = sCI[tid * 4 + q];
            float2 cs = sCS[tid * 4 + q];
            scv[2*q] = cs.x;   idv[2*q] = ci.x;
            scv[2*q+1] = cs.y; idv[2*q+1] = ci.y;
        }
        float bs = scv[0];
#pragma unroll
        for (int q = 1; q < 8; q++) bs = fmaxf(bs, scv[q]);

        float4 zr[D / 4];
        const float4* zp = (const float4*)(z + (size_t)row * D);
#pragma unroll
        for (int j = 0; j < D / 4; j++) zr[j] = zp[j];

        float bd2 = 3.4e38f; int bidx = K;
#pragma unroll 1
        for (int q = 0; q < 8; q++) {
            if (scv[q] >= bs - TH) {
                const float4* wv = (const float4*)(weight + (size_t)idv[q] * D);
                float d2 = 0.0f;
#pragma unroll
                for (int j = 0; j < D / 4; j++) {
                    float4 w = wv[j];
                    float dx = zr[j].x - w.x, dy = zr[j].y - w.y;
                    float dz = zr[j].z - w.z, dw = zr[j].w - w.w;
                    d2 = fmaf(dx, dx, d2); d2 = fmaf(dy, dy, d2);
                    d2 = fmaf(dz, dz, d2); d2 = fmaf(dw, dw, d2);
                }
                if (d2 < bd2 || (d2 == bd2 && idv[q] < bidx)) { bd2 = d2; bidx = idv[q]; }
            }
        }

        const float4* wv = (const float4*)(weight + (size_t)bidx * D);
        float4* op = (float4*)(out_zq + (size_t)row * D);
        float* eb = g_embed + (size_t)bidx * D;
#pragma unroll
        for (int j = 0; j < D / 4; j++) {
            op[j] = wv[j];
            red_add_v4(eb + 4 * j, zr[j]);
        }
        out_idx[row] = (float)bidx;
        atomicAdd(&sHist[bidx], 1u);

        float d2 = bd2;
#pragma unroll
        for (int o = 16; o; o >>= 1) d2 += __shfl_xor_sync(0xffffffffu, d2, o);
        if (lane == 0) atomicAdd(&g_loss, d2);
    }
    __syncthreads();
    for (int i = tid; i < K; i += NT) {
        unsigned int c = sHist[i];
        if (c) atomicAdd(&g_counts[i], c);
    }
}

// ---------------- finalize ----------------
__global__ void vq_finalA(const float* __restrict__ ema_cs, float* __restrict__ out) {
    __shared__ float sSum[K];
    int k = threadIdx.x;
    float ncs = fmaf(0.99f, ema_cs[k], 0.01f * (float)g_counts[k]);
    out[OFF_CS + k] = ncs;
    sSum[k] = ncs;
    __syncthreads();
#pragma unroll
    for (int s = K / 2; s > 0; s >>= 1) {
        if (k < s) sSum[k] += sSum[k + s];
        __syncthreads();
    }
    if (k == 0) {
        g_n = sSum[0];
        out[OFF_LOSS] = 0.25f * g_loss / (float)(B_TOTAL * D);
    }
}

__global__ void vq_finalB(const float* __restrict__ ema_es,
                          const float* __restrict__ ema_cs,
                          float* __restrict__ out) {
    int i = blockIdx.x * blockDim.x + threadIdx.x;
    if (i >= K * D) return;
    int k = i >> 6;
    float nes = fmaf(0.99f, ema_es[i], 0.01f * g_embed[i]);
    out[OFF_ES + i] = nes;
    float ncs = fmaf(0.99f, ema_cs[k], 0.01f * (float)g_counts[k]);
    float n = g_n;
    float smoothed = (ncs + 1e-5f) / (n + (float)K * 1e-5f) * n;
    out[OFF_W + i] = nes / smoothed;
}

extern "C" void kernel_launch(void* const* d_in, const int* in_sizes, int n_in,
                              void* d_out, int out_size) {
    const float* z      = (const float*)d_in[0];
    const float* weight = (const float*)d_in[1];
    const float* ema_cs = (const float*)d_in[2];
    const float* ema_es = (const float*)d_in[3];
    float* out = (float*)d_out;

    cudaFuncSetAttribute(vq_main, cudaFuncAttributeMaxDynamicSharedMemorySize, SM_TOTAL);

    vq_zero<<<(K * D + 255) / 256, 256>>>();
    vq_prep<<<(K + 255) / 256, 256>>>(weight);
    vq_main<<<B_TOTAL / M_CTA, NT, SM_TOTAL>>>(z, weight, out + OFF_ZQ, out + OFF_IDX);
    vq_finalA<<<1, K>>>(ema_cs, out);
    vq_finalB<<<(K * D + 255) / 256, 256>>>(ema_es, ema_cs, out);
}

// round 7
// speedup vs baseline: 3.6084x; 1.4488x over previous
#include <cuda_runtime.h>
#include <cuda_bf16.h>
#include <cstdint>

// ---------------- problem constants ----------------
#define B_TOTAL 262144
#define D 64
#define K 1024
#define M_CTA 256            // rows per CTA
#define NT 256               // threads per CTA
#define TH 0.16f

// Output layout (float32, reference return order)
#define OFF_ZQ    0
#define OFF_IDX   16777216            // B*D
#define OFF_LOSS  17039360            // + B
#define OFF_CS    17039361            // + 1
#define OFF_ES    17040385            // + K
#define OFF_W     17105921            // + K*D

// ---------------- device scratch (no cudaMalloc allowed) ----------------
__device__ float          g_wsq[K];      // -0.5*||w||^2
__device__ unsigned int   g_counts[K];
__device__ float          g_embed[K * D];
__device__ float          g_loss;
__device__ float          g_n;
__device__ __nv_bfloat16  g_wh[K * D];

// ---------------- dynamic smem layout (bytes) ----------------
#define SM_SH   0          // 128 x 144B: z-hi staging, then codebook tile buf0
#define SM_SL   18432      // 128 x 144B: z-lo staging, then codebook tile buf1
#define SM_W2   36864      // 1024 f32
#define SM_HIST 40960      // 1024 u32
#define SM_CI   45056      // uint2 [256][4] packed top-2
#define SM_TOTAL 53248

__device__ __forceinline__ void red_add_v4(float* p, float4 v) {
    asm volatile("red.global.add.v4.f32 [%0], {%1,%2,%3,%4};"
                 :: "l"(p), "f"(v.x), "f"(v.y), "f"(v.z), "f"(v.w) : "memory");
}

__device__ __forceinline__ void mma16816(float c[4], const uint32_t a[4],
                                         uint32_t b0, uint32_t b1) {
    asm volatile("mma.sync.aligned.m16n8k16.row.col.f32.bf16.bf16.f32 "
                 "{%0,%1,%2,%3}, {%4,%5,%6,%7}, {%8,%9}, {%0,%1,%2,%3};"
                 : "+f"(c[0]), "+f"(c[1]), "+f"(c[2]), "+f"(c[3])
                 : "r"(a[0]), "r"(a[1]), "r"(a[2]), "r"(a[3]), "r"(b0), "r"(b1));
}

__device__ __forceinline__ void ldmx4(uint32_t r[4], uint32_t saddr) {
    asm volatile("ldmatrix.sync.aligned.m8n8.x4.shared.b16 {%0,%1,%2,%3}, [%4];"
                 : "=r"(r[0]), "=r"(r[1]), "=r"(r[2]), "=r"(r[3]) : "r"(saddr));
}

__device__ __forceinline__ void cpasync16(uint32_t dst, const void* src) {
    asm volatile("cp.async.ca.shared.global [%0], [%1], 16;"
                 :: "r"(dst), "l"(src) : "memory");
}

// float -> orderable u32, strip 10 LSBs, insert 10-bit code index
__device__ __forceinline__ uint32_t packsc(float s, int col) {
    int iv = __float_as_int(s);
    uint32_t u = (uint32_t)iv ^ (0x80000000u | (uint32_t)(iv >> 31));
    return (u & 0xFFFFFC00u) | (uint32_t)col;
}
__device__ __forceinline__ void unpacksc(uint32_t pk, float& s, int& col) {
    col = (int)(pk & 1023u);
    uint32_t u = pk & 0xFFFFFC00u;
    int iv = (u & 0x80000000u) ? (int)(u ^ 0x80000000u) : (int)~u;
    s = __int_as_float(iv);
}

// ---------------- zero scratch ----------------
__global__ void vq_zero() {
    int i = blockIdx.x * blockDim.x + threadIdx.x;
    if (i < K * D) g_embed[i] = 0.0f;
    if (i < K)     g_counts[i] = 0u;
    if (i == 0)    g_loss = 0.0f;
}

// ---------------- prep: bf16 codebook + (-0.5*w2) ----------------
__global__ void vq_prep(const float* __restrict__ weight) {
    int k = blockIdx.x * blockDim.x + threadIdx.x;
    if (k >= K) return;
    const float4* wp = (const float4*)(weight + (size_t)k * D);
    float s = 0.0f;
    for (int j = 0; j < D / 4; j++) {
        float4 v = wp[j];
        s = fmaf(v.x, v.x, s); s = fmaf(v.y, v.y, s);
        s = fmaf(v.z, v.z, s); s = fmaf(v.w, v.w, s);
        __nv_bfloat162 p0 = __floats2bfloat162_rn(v.x, v.y);
        __nv_bfloat162 p1 = __floats2bfloat162_rn(v.z, v.w);
        uint2 H = make_uint2(*(uint32_t*)&p0, *(uint32_t*)&p1);
        ((uint2*)(g_wh + (size_t)k * D))[j] = H;
    }
    g_wsq[k] = -0.5f * s;
}

// ---------------- main fused kernel ----------------
__global__ __launch_bounds__(NT, 2)
void vq_main(const float* __restrict__ z,
             const float* __restrict__ weight,
             float* __restrict__ out_zq,
             float* __restrict__ out_idx) {
    extern __shared__ char sm[];
    const uint32_t smu = (uint32_t)__cvta_generic_to_shared(sm);
    const int tid  = threadIdx.x;
    const int wid  = tid >> 5;
    const int lane = tid & 31;
    const int wrb  = wid * 32;
    const int row0 = blockIdx.x * M_CTA;

    char*         sH    = sm + SM_SH;
    char*         sL    = sm + SM_SL;
    float*        sW2n  = (float*)(sm + SM_W2);
    unsigned int* sHist = (unsigned int*)(sm + SM_HIST);
    uint2*        sCI   = (uint2*)(sm + SM_CI);

    for (int i = tid; i < K; i += NT) { sW2n[i] = g_wsq[i]; sHist[i] = 0u; }

    // ---- phase 1: stage z (two halves of 128 rows), build A fragments ----
    uint32_t aH[2][4][4], aL[2][4][4];
    const int sr = tid >> 1;
    const int sc = (tid & 1) * 32;
#pragma unroll 1
    for (int h = 0; h < 2; h++) {
        __syncthreads();
        {
            const float4* zp = (const float4*)(z + ((size_t)(row0 + h * 128 + sr)) * D + sc);
            uint2* dH = (uint2*)(sH + sr * 144 + sc * 2);
            uint2* dL = (uint2*)(sL + sr * 144 + sc * 2);
#pragma unroll
            for (int j = 0; j < 8; j++) {
                float4 v = zp[j];
                float f[4] = {v.x, v.y, v.z, v.w};
                unsigned short hh[4], ll[4];
#pragma unroll
                for (int e = 0; e < 4; e++) {
                    __nv_bfloat16 bh = __float2bfloat16_rn(f[e]);
                    float fh = __bfloat162float(bh);
                    __nv_bfloat16 bl = __float2bfloat16_rn(f[e] - fh);
                    hh[e] = __bfloat16_as_ushort(bh);
                    ll[e] = __bfloat16_as_ushort(bl);
                }
                uint2 H, L;
                H.x = (uint32_t)hh[0] | ((uint32_t)hh[1] << 16);
                H.y = (uint32_t)hh[2] | ((uint32_t)hh[3] << 16);
                L.x = (uint32_t)ll[0] | ((uint32_t)ll[1] << 16);
                L.y = (uint32_t)ll[2] | ((uint32_t)ll[3] << 16);
                dH[j] = H; dL[j] = L;
            }
        }
        __syncthreads();
        if ((wid >> 2) == h) {
            const int br = (wid & 3) * 32;
#pragma unroll
            for (int f = 0; f < 2; f++)
#pragma unroll
            for (int kk = 0; kk < 4; kk++) {
                int rr = br + f * 16 + (lane >> 2);
                int cb = (kk * 16 + (lane & 3) * 2) * 2;
                aH[f][kk][0] = *(const uint32_t*)(sH + rr * 144 + cb);
                aH[f][kk][1] = *(const uint32_t*)(sH + (rr + 8) * 144 + cb);
                aH[f][kk][2] = *(const uint32_t*)(sH + rr * 144 + cb + 16);
                aH[f][kk][3] = *(const uint32_t*)(sH + (rr + 8) * 144 + cb + 16);
                aL[f][kk][0] = *(const uint32_t*)(sL + rr * 144 + cb);
                aL[f][kk][1] = *(const uint32_t*)(sL + (rr + 8) * 144 + cb);
                aL[f][kk][2] = *(const uint32_t*)(sL + rr * 144 + cb + 16);
                aL[f][kk][3] = *(const uint32_t*)(sL + (rr + 8) * 144 + cb + 16);
            }
        }
    }
    __syncthreads();   // all frag reads done; sH/sL become codebook tile buffers

    // prefetch codebook tile 0 -> buf0 (sH)
    {
        const __nv_bfloat16* src = g_wh + (size_t)sr * D + sc;
        uint32_t dst = smu + SM_SH + sr * 144 + sc * 2;
#pragma unroll
        for (int j = 0; j < 4; j++) cpasync16(dst + j * 16, src + j * 8);
        asm volatile("cp.async.commit_group;" ::: "memory");
    }

    // ldmatrix B addressing
    const uint32_t lmB = (uint32_t)((lane & 7) * 144 + (lane >> 3) * 16);

    // ---- phase 2: stream codebook tiles, HMMA (2 passes), packed top-2 ----
    uint32_t pk1[4], pk2[4];
#pragma unroll
    for (int s = 0; s < 4; s++) { pk1[s] = 0u; pk2[s] = 0u; }

#pragma unroll 1
    for (int t = 0; t < K / 128; t++) {
        if (t < 7) {
            const __nv_bfloat16* src = g_wh + ((size_t)(t + 1) * 128 + sr) * D + sc;
            uint32_t dst = smu + ((t + 1) & 1 ? SM_SL : SM_SH) + sr * 144 + sc * 2;
#pragma unroll
            for (int j = 0; j < 4; j++) cpasync16(dst + j * 16, src + j * 8);
            asm volatile("cp.async.commit_group;" ::: "memory");
            asm volatile("cp.async.wait_group 1;" ::: "memory");
        } else {
            asm volatile("cp.async.wait_group 0;" ::: "memory");
        }
        __syncthreads();

        const uint32_t tbase = smu + ((t & 1) ? SM_SL : SM_SH);
#pragma unroll 1
        for (int nb = 0; nb < 16; nb++) {
            const int colb = t * 128 + nb * 8 + (lane & 3) * 2;
            float2 w2 = *(const float2*)&sW2n[colb];

            uint32_t bh[8];
            {
                uint32_t base = tbase + (uint32_t)(nb * 8) * 144u + lmB;
                ldmx4(bh,     base);
                ldmx4(bh + 4, base + 64);
            }

            float cA0[4] = {0.f, 0.f, 0.f, 0.f};
            float cA1[4] = {0.f, 0.f, 0.f, 0.f};
            float cB0[4] = {0.f, 0.f, 0.f, 0.f};
            float cB1[4] = {0.f, 0.f, 0.f, 0.f};

#pragma unroll
            for (int kk = 0; kk < 4; kk++) {
                float* t0 = (kk & 1) ? cB0 : cA0;
                float* t1 = (kk & 1) ? cB1 : cA1;
                mma16816(t0, aH[0][kk], bh[2 * kk], bh[2 * kk + 1]);
                mma16816(t1, aH[1][kk], bh[2 * kk], bh[2 * kk + 1]);
            }
#pragma unroll
            for (int kk = 0; kk < 4; kk++) {
                float* t0 = (kk & 1) ? cB0 : cA0;
                float* t1 = (kk & 1) ? cB1 : cA1;
                mma16816(t0, aL[0][kk], bh[2 * kk], bh[2 * kk + 1]);
                mma16816(t1, aL[1][kk], bh[2 * kk], bh[2 * kk + 1]);
            }

            // scores + packed branch-free top-2 per s (IMNMX only)
            float v0 = (cA0[0] + cB0[0]) + w2.x;
            float v1 = (cA0[1] + cB0[1]) + w2.y;
            float v2 = (cA0[2] + cB0[2]) + w2.x;
            float v3 = (cA0[3] + cB0[3]) + w2.y;
            float v4 = (cA1[0] + cB1[0]) + w2.x;
            float v5 = (cA1[1] + cB1[1]) + w2.y;
            float v6 = (cA1[2] + cB1[2]) + w2.x;
            float v7 = (cA1[3] + cB1[3]) + w2.y;
#define TOP2(s, va, vb) do {                                                  \
                uint32_t _p0 = packsc(va, colb);                              \
                uint32_t _p1 = packsc(vb, colb + 1);                          \
                uint32_t _m1 = max(_p0, _p1), _m2 = min(_p0, _p1);            \
                uint32_t _nm = max(pk1[s], _m1);                              \
                pk2[s] = max(pk2[s], max(min(pk1[s], _m1), _m2));             \
                pk1[s] = _nm;                                                 \
            } while (0)
            TOP2(0, v0, v1);
            TOP2(1, v2, v3);
            TOP2(2, v4, v5);
            TOP2(3, v6, v7);
#undef TOP2
        }
        __syncthreads();   // all warps done with buf[t&1] before it is re-prefetched
    }

    // ---- write per-lane packed candidates (8 per row) ----
#pragma unroll
    for (int s = 0; s < 4; s++) {
        int rl = wrb + (lane >> 2) + 8 * s;
        sCI[rl * 4 + (lane & 3)] = make_uint2(pk1[s], pk2[s]);
    }
    __syncthreads();

    // ---- epilogue: exact fp32 re-check of candidates near the approx best ----
    {
        const int row = row0 + tid;
        float scv[8]; int idv[8];
#pragma unroll
        for (int q = 0; q < 4; q++) {
            uint2 c = sCI[tid * 4 + q];
            unpacksc(c.x, scv[2 * q],     idv[2 * q]);
            unpacksc(c.y, scv[2 * q + 1], idv[2 * q + 1]);
        }
        float bs = scv[0];
#pragma unroll
        for (int q = 1; q < 8; q++) bs = fmaxf(bs, scv[q]);

        float4 zr[D / 4];
        const float4* zp = (const float4*)(z + (size_t)row * D);
#pragma unroll
        for (int j = 0; j < D / 4; j++) zr[j] = zp[j];

        float bd2 = 3.4e38f; int bidx = K;
#pragma unroll 1
        for (int q = 0; q < 8; q++) {
            if (scv[q] >= bs - TH) {
                const float4* wv = (const float4*)(weight + (size_t)idv[q] * D);
                float d2 = 0.0f;
#pragma unroll
                for (int j = 0; j < D / 4; j++) {
                    float4 w = wv[j];
                    float dx = zr[j].x - w.x, dy = zr[j].y - w.y;
                    float dz = zr[j].z - w.z, dw = zr[j].w - w.w;
                    d2 = fmaf(dx, dx, d2); d2 = fmaf(dy, dy, d2);
                    d2 = fmaf(dz, dz, d2); d2 = fmaf(dw, dw, d2);
                }
                if (d2 < bd2 || (d2 == bd2 && idv[q] < bidx)) { bd2 = d2; bidx = idv[q]; }
            }
        }

        const float4* wv = (const float4*)(weight + (size_t)bidx * D);
        float4* op = (float4*)(out_zq + (size_t)row * D);
        float* eb = g_embed + (size_t)bidx * D;
#pragma unroll
        for (int j = 0; j < D / 4; j++) {
            op[j] = wv[j];
            red_add_v4(eb + 4 * j, zr[j]);
        }
        out_idx[row] = (float)bidx;
        atomicAdd(&sHist[bidx], 1u);

        float d2 = bd2;
#pragma unroll
        for (int o = 16; o; o >>= 1) d2 += __shfl_xor_sync(0xffffffffu, d2, o);
        if (lane == 0) atomicAdd(&g_loss, d2);
    }
    __syncthreads();
    for (int i = tid; i < K; i += NT) {
        unsigned int c = sHist[i];
        if (c) atomicAdd(&g_counts[i], c);
    }
}

// ---------------- finalize ----------------
__global__ void vq_finalA(const float* __restrict__ ema_cs, float* __restrict__ out) {
    __shared__ float sSum[K];
    int k = threadIdx.x;
    float ncs = fmaf(0.99f, ema_cs[k], 0.01f * (float)g_counts[k]);
    out[OFF_CS + k] = ncs;
    sSum[k] = ncs;
    __syncthreads();
#pragma unroll
    for (int s = K / 2; s > 0; s >>= 1) {
        if (k < s) sSum[k] += sSum[k + s];
        __syncthreads();
    }
    if (k == 0) {
        g_n = sSum[0];
        out[OFF_LOSS] = 0.25f * g_loss / (float)(B_TOTAL * D);
    }
}

__global__ void vq_finalB(const float* __restrict__ ema_es,
                          const float* __restrict__ ema_cs,
                          float* __restrict__ out) {
    int i = blockIdx.x * blockDim.x + threadIdx.x;
    if (i >= K * D) return;
    int k = i >> 6;
    float nes = fmaf(0.99f, ema_es[i], 0.01f * g_embed[i]);
    out[OFF_ES + i] = nes;
    float ncs = fmaf(0.99f, ema_cs[k], 0.01f * (float)g_counts[k]);
    float n = g_n;
    float smoothed = (ncs + 1e-5f) / (n + (float)K * 1e-5f) * n;
    out[OFF_W + i] = nes / smoothed;
}

extern "C" void kernel_launch(void* const* d_in, const int* in_sizes, int n_in,
                              void* d_out, int out_size) {
    const float* z      = (const float*)d_in[0];
    const float* weight = (const float*)d_in[1];
    const float* ema_cs = (const float*)d_in[2];
    const float* ema_es = (const float*)d_in[3];
    float* out = (float*)d_out;

    cudaFuncSetAttribute(vq_main, cudaFuncAttributeMaxDynamicSharedMemorySize, SM_TOTAL);

    vq_zero<<<(K * D + 255) / 256, 256>>>();
    vq_prep<<<(K + 255) / 256, 256>>>(weight);
    vq_main<<<B_TOTAL / M_CTA, NT, SM_TOTAL>>>(z, weight, out + OFF_ZQ, out + OFF_IDX);
    vq_finalA<<<1, K>>>(ema_cs, out);
    vq_finalB<<<(K * D + 255) / 256, 256>>>(ema_es, ema_cs, out);
}

// round 9
// speedup vs baseline: 3.6126x; 1.0011x over previous
#include <cuda_runtime.h>
#include <cuda_bf16.h>
#include <cstdint>

// ---------------- problem constants ----------------
#define B_TOTAL 262144
#define D 64
#define K 1024
#define M_CTA 256            // rows per CTA
#define NT 256               // threads per CTA
#define TH 0.16f
#define BIAS 128.0f          // score bias: keeps all scores strictly positive

// Output layout (float32, reference return order)
#define OFF_ZQ    0
#define OFF_IDX   16777216            // B*D
#define OFF_LOSS  17039360            // + B
#define OFF_CS    17039361            // + 1
#define OFF_ES    17040385            // + K
#define OFF_W     17105921            // + K*D

// ---------------- device scratch (no cudaMalloc allowed) ----------------
__device__ float          g_wsq[K];      // BIAS - 0.5*||w||^2
__device__ unsigned int   g_counts[K];
__device__ float          g_embed[K * D];
__device__ float          g_loss;
__device__ float          g_n;
__device__ __nv_bfloat16  g_wh[K * D];

// ---------------- dynamic smem layout (bytes) ----------------
#define SM_SH   0          // 128 x 144B: z-hi staging, then codebook tile buf0
#define SM_SL   18432      // 128 x 144B: z-lo staging, then codebook tile buf1
#define SM_W2   36864      // 1024 f32
#define SM_HIST 40960      // 1024 u32
#define SM_CI   45056      // uint2 [256][4] packed top-2
#define SM_TOTAL 53248

__device__ __forceinline__ void red_add_v4(float* p, float4 v) {
    asm volatile("red.global.add.v4.f32 [%0], {%1,%2,%3,%4};"
                 :: "l"(p), "f"(v.x), "f"(v.y), "f"(v.z), "f"(v.w) : "memory");
}

__device__ __forceinline__ void mma16816(float c[4], const uint32_t a[4],
                                         uint32_t b0, uint32_t b1) {
    asm volatile("mma.sync.aligned.m16n8k16.row.col.f32.bf16.bf16.f32 "
                 "{%0,%1,%2,%3}, {%4,%5,%6,%7}, {%8,%9}, {%0,%1,%2,%3};"
                 : "+f"(c[0]), "+f"(c[1]), "+f"(c[2]), "+f"(c[3])
                 : "r"(a[0]), "r"(a[1]), "r"(a[2]), "r"(a[3]), "r"(b0), "r"(b1));
}

__device__ __forceinline__ void ldmx4(uint32_t r[4], uint32_t saddr) {
    asm volatile("ldmatrix.sync.aligned.m8n8.x4.shared.b16 {%0,%1,%2,%3}, [%4];"
                 : "=r"(r[0]), "=r"(r[1]), "=r"(r[2]), "=r"(r[3]) : "r"(saddr));
}

__device__ __forceinline__ void cpasync16(uint32_t dst, const void* src) {
    asm volatile("cp.async.ca.shared.global [%0], [%1], 16;"
                 :: "r"(dst), "l"(src) : "memory");
}

// scores are strictly positive -> float bits order as unsigned ints
__device__ __forceinline__ uint32_t packsc(float s, int col) {
    return (__float_as_uint(s) & 0xFFFFFC00u) | (uint32_t)col;
}
__device__ __forceinline__ void unpacksc(uint32_t pk, float& s, int& col) {
    col = (int)(pk & 1023u);
    s = __uint_as_float(pk & 0xFFFFFC00u);
}

// ---------------- zero scratch ----------------
__global__ void vq_zero() {
    int i = blockIdx.x * blockDim.x + threadIdx.x;
    if (i < K * D) g_embed[i] = 0.0f;
    if (i < K)     g_counts[i] = 0u;
    if (i == 0)    g_loss = 0.0f;
}

// ---------------- prep: bf16 codebook + (BIAS - 0.5*w2) ----------------
__global__ void vq_prep(const float* __restrict__ weight) {
    int k = blockIdx.x * blockDim.x + threadIdx.x;
    if (k >= K) return;
    const float4* wp = (const float4*)(weight + (size_t)k * D);
    float s = 0.0f;
    for (int j = 0; j < D / 4; j++) {
        float4 v = wp[j];
        s = fmaf(v.x, v.x, s); s = fmaf(v.y, v.y, s);
        s = fmaf(v.z, v.z, s); s = fmaf(v.w, v.w, s);
        __nv_bfloat162 p0 = __floats2bfloat162_rn(v.x, v.y);
        __nv_bfloat162 p1 = __floats2bfloat162_rn(v.z, v.w);
        uint2 H = make_uint2(*(uint32_t*)&p0, *(uint32_t*)&p1);
        ((uint2*)(g_wh + (size_t)k * D))[j] = H;
    }
    g_wsq[k] = BIAS - 0.5f * s;
}

// ---------------- main fused kernel ----------------
__global__ __launch_bounds__(NT, 2)
void vq_main(const float* __restrict__ z,
             const float* __restrict__ weight,
             float* __restrict__ out_zq,
             float* __restrict__ out_idx) {
    extern __shared__ char sm[];
    const uint32_t smu = (uint32_t)__cvta_generic_to_shared(sm);
    const int tid  = threadIdx.x;
    const int wid  = tid >> 5;
    const int lane = tid & 31;
    const int wrb  = wid * 32;
    const int row0 = blockIdx.x * M_CTA;

    char*         sH    = sm + SM_SH;
    char*         sL    = sm + SM_SL;
    float*        sW2n  = (float*)(sm + SM_W2);
    unsigned int* sHist = (unsigned int*)(sm + SM_HIST);
    uint2*        sCI   = (uint2*)(sm + SM_CI);

    for (int i = tid; i < K; i += NT) { sW2n[i] = g_wsq[i]; sHist[i] = 0u; }

    // ---- phase 1: stage z (two halves of 128 rows), build A fragments ----
    uint32_t aH[2][4][4], aL[2][4][4];
    const int sr = tid >> 1;
    const int sc = (tid & 1) * 32;
#pragma unroll 1
    for (int h = 0; h < 2; h++) {
        __syncthreads();
        {
            const float4* zp = (const float4*)(z + ((size_t)(row0 + h * 128 + sr)) * D + sc);
            uint2* dH = (uint2*)(sH + sr * 144 + sc * 2);
            uint2* dL = (uint2*)(sL + sr * 144 + sc * 2);
#pragma unroll
            for (int j = 0; j < 8; j++) {
                float4 v = zp[j];
                float f[4] = {v.x, v.y, v.z, v.w};
                unsigned short hh[4], ll[4];
#pragma unroll
                for (int e = 0; e < 4; e++) {
                    __nv_bfloat16 bh = __float2bfloat16_rn(f[e]);
                    float fh = __bfloat162float(bh);
                    __nv_bfloat16 bl = __float2bfloat16_rn(f[e] - fh);
                    hh[e] = __bfloat16_as_ushort(bh);
                    ll[e] = __bfloat16_as_ushort(bl);
                }
                uint2 H, L;
                H.x = (uint32_t)hh[0] | ((uint32_t)hh[1] << 16);
                H.y = (uint32_t)hh[2] | ((uint32_t)hh[3] << 16);
                L.x = (uint32_t)ll[0] | ((uint32_t)ll[1] << 16);
                L.y = (uint32_t)ll[2] | ((uint32_t)ll[3] << 16);
                dH[j] = H; dL[j] = L;
            }
        }
        __syncthreads();
        if ((wid >> 2) == h) {
            const int br = (wid & 3) * 32;
#pragma unroll
            for (int f = 0; f < 2; f++)
#pragma unroll
            for (int kk = 0; kk < 4; kk++) {
                int rr = br + f * 16 + (lane >> 2);
                int cb = (kk * 16 + (lane & 3) * 2) * 2;
                aH[f][kk][0] = *(const uint32_t*)(sH + rr * 144 + cb);
                aH[f][kk][1] = *(const uint32_t*)(sH + (rr + 8) * 144 + cb);
                aH[f][kk][2] = *(const uint32_t*)(sH + rr * 144 + cb + 16);
                aH[f][kk][3] = *(const uint32_t*)(sH + (rr + 8) * 144 + cb + 16);
                aL[f][kk][0] = *(const uint32_t*)(sL + rr * 144 + cb);
                aL[f][kk][1] = *(const uint32_t*)(sL + (rr + 8) * 144 + cb);
                aL[f][kk][2] = *(const uint32_t*)(sL + rr * 144 + cb + 16);
                aL[f][kk][3] = *(const uint32_t*)(sL + (rr + 8) * 144 + cb + 16);
            }
        }
    }
    __syncthreads();   // all frag reads done; sH/sL become codebook tile buffers

    // prefetch codebook tile 0 -> buf0 (sH)
    {
        const __nv_bfloat16* src = g_wh + (size_t)sr * D + sc;
        uint32_t dst = smu + SM_SH + sr * 144 + sc * 2;
#pragma unroll
        for (int j = 0; j < 4; j++) cpasync16(dst + j * 16, src + j * 8);
        asm volatile("cp.async.commit_group;" ::: "memory");
    }

    // ldmatrix B addressing
    const uint32_t lmB = (uint32_t)((lane & 7) * 144 + (lane >> 3) * 16);

    // ---- phase 2: stream codebook tiles, HMMA (2 passes), packed top-2 ----
    uint32_t pk1[4], pk2[4];
#pragma unroll
    for (int s = 0; s < 4; s++) { pk1[s] = 0u; pk2[s] = 0u; }

#pragma unroll 1
    for (int t = 0; t < K / 128; t++) {
        if (t < 7) {
            const __nv_bfloat16* src = g_wh + ((size_t)(t + 1) * 128 + sr) * D + sc;
            uint32_t dst = smu + ((t + 1) & 1 ? SM_SL : SM_SH) + sr * 144 + sc * 2;
#pragma unroll
            for (int j = 0; j < 4; j++) cpasync16(dst + j * 16, src + j * 8);
            asm volatile("cp.async.commit_group;" ::: "memory");
            asm volatile("cp.async.wait_group 1;" ::: "memory");
        } else {
            asm volatile("cp.async.wait_group 0;" ::: "memory");
        }
        __syncthreads();

        const uint32_t tbase = smu + ((t & 1) ? SM_SL : SM_SH);
#pragma unroll 1
        for (int nb = 0; nb < 16; nb++) {
            const int colb = t * 128 + nb * 8 + (lane & 3) * 2;
            float2 w2 = *(const float2*)&sW2n[colb];

            uint32_t bh[8];
            {
                uint32_t base = tbase + (uint32_t)(nb * 8) * 144u + lmB;
                ldmx4(bh,     base);
                ldmx4(bh + 4, base + 64);
            }

            // single accumulator set, initialized with biased -0.5*w2
            float c0[4] = {w2.x, w2.y, w2.x, w2.y};
            float c1[4] = {w2.x, w2.y, w2.x, w2.y};

#pragma unroll
            for (int kk = 0; kk < 4; kk++) {
                mma16816(c0, aH[0][kk], bh[2 * kk], bh[2 * kk + 1]);
                mma16816(c1, aH[1][kk], bh[2 * kk], bh[2 * kk + 1]);
            }
#pragma unroll
            for (int kk = 0; kk < 4; kk++) {
                mma16816(c0, aL[0][kk], bh[2 * kk], bh[2 * kk + 1]);
                mma16816(c1, aL[1][kk], bh[2 * kk], bh[2 * kk + 1]);
            }

            // branch-free FULL top-2 on packed positive-float bits
#define TOP2(s, va, vb) do {                                                  \
                uint32_t _p0 = packsc(va, colb);                              \
                uint32_t _p1 = packsc(vb, colb + 1);                          \
                uint32_t _m1 = max(_p0, _p1), _m2 = min(_p0, _p1);            \
                pk2[s] = max(pk2[s], max(min(pk1[s], _m1), _m2));             \
                pk1[s] = max(pk1[s], _m1);                                    \
            } while (0)
            TOP2(0, c0[0], c0[1]);
            TOP2(1, c0[2], c0[3]);
            TOP2(2, c1[0], c1[1]);
            TOP2(3, c1[2], c1[3]);
#undef TOP2
        }
        __syncthreads();   // all warps done with buf[t&1] before it is re-prefetched
    }

    // ---- write per-lane packed candidates (8 per row) ----
#pragma unroll
    for (int s = 0; s < 4; s++) {
        int rl = wrb + (lane >> 2) + 8 * s;
        sCI[rl * 4 + (lane & 3)] = make_uint2(pk1[s], pk2[s]);
    }
    __syncthreads();

    // ---- epilogue: exact fp32 re-check of candidates near the approx best ----
    {
        const int row = row0 + tid;
        float scv[8]; int idv[8];
#pragma unroll
        for (int q = 0; q < 4; q++) {
            uint2 c = sCI[tid * 4 + q];
            unpacksc(c.x, scv[2 * q],     idv[2 * q]);
            unpacksc(c.y, scv[2 * q + 1], idv[2 * q + 1]);
        }
        float bs = scv[0];
#pragma unroll
        for (int q = 1; q < 8; q++) bs = fmaxf(bs, scv[q]);

        float4 zr[D / 4];
        const float4* zp = (const float4*)(z + (size_t)row * D);
#pragma unroll
        for (int j = 0; j < D / 4; j++) zr[j] = zp[j];

        float bd2 = 3.4e38f; int bidx = K;
#pragma unroll 1
        for (int q = 0; q < 8; q++) {
            if (scv[q] >= bs - TH) {
                const float4* wv = (const float4*)(weight + (size_t)idv[q] * D);
                float d2 = 0.0f;
#pragma unroll
                for (int j = 0; j < D / 4; j++) {
                    float4 w = wv[j];
                    float dx = zr[j].x - w.x, dy = zr[j].y - w.y;
                    float dz = zr[j].z - w.z, dw = zr[j].w - w.w;
                    d2 = fmaf(dx, dx, d2); d2 = fmaf(dy, dy, d2);
                    d2 = fmaf(dz, dz, d2); d2 = fmaf(dw, dw, d2);
                }
                if (d2 < bd2 || (d2 == bd2 && idv[q] < bidx)) { bd2 = d2; bidx = idv[q]; }
            }
        }

        const float4* wv = (const float4*)(weight + (size_t)bidx * D);
        float4* op = (float4*)(out_zq + (size_t)row * D);
        float* eb = g_embed + (size_t)bidx * D;
#pragma unroll
        for (int j = 0; j < D / 4; j++) {
            op[j] = wv[j];
            red_add_v4(eb + 4 * j, zr[j]);
        }
        out_idx[row] = (float)bidx;
        atomicAdd(&sHist[bidx], 1u);

        float d2 = bd2;
#pragma unroll
        for (int o = 16; o; o >>= 1) d2 += __shfl_xor_sync(0xffffffffu, d2, o);
        if (lane == 0) atomicAdd(&g_loss, d2);
    }
    __syncthreads();
    for (int i = tid; i < K; i += NT) {
        unsigned int c = sHist[i];
        if (c) atomicAdd(&g_counts[i], c);
    }
}

// ---------------- finalize ----------------
__global__ void vq_finalA(const float* __restrict__ ema_cs, float* __restrict__ out) {
    __shared__ float sSum[K];
    int k = threadIdx.x;
    float ncs = fmaf(0.99f, ema_cs[k], 0.01f * (float)g_counts[k]);
    out[OFF_CS + k] = ncs;
    sSum[k] = ncs;
    __syncthreads();
#pragma unroll
    for (int s = K / 2; s > 0; s >>= 1) {
        if (k < s) sSum[k] += sSum[k + s];
        __syncthreads();
    }
    if (k == 0) {
        g_n = sSum[0];
        out[OFF_LOSS] = 0.25f * g_loss / (float)(B_TOTAL * D);
    }
}

__global__ void vq_finalB(const float* __restrict__ ema_es,
                          const float* __restrict__ ema_cs,
                          float* __restrict__ out) {
    int i = blockIdx.x * blockDim.x + threadIdx.x;
    if (i >= K * D) return;
    int k = i >> 6;
    float nes = fmaf(0.99f, ema_es[i], 0.01f * g_embed[i]);
    out[OFF_ES + i] = nes;
    float ncs = fmaf(0.99f, ema_cs[k], 0.01f * (float)g_counts[k]);
    float n = g_n;
    float smoothed = (ncs + 1e-5f) / (n + (float)K * 1e-5f) * n;
    out[OFF_W + i] = nes / smoothed;
}

extern "C" void kernel_launch(void* const* d_in, const int* in_sizes, int n_in,
                              void* d_out, int out_size) {
    const float* z      = (const float*)d_in[0];
    const float* weight = (const float*)d_in[1];
    const float* ema_cs = (const float*)d_in[2];
    const float* ema_es = (const float*)d_in[3];
    float* out = (float*)d_out;

    cudaFuncSetAttribute(vq_main, cudaFuncAttributeMaxDynamicSharedMemorySize, SM_TOTAL);

    vq_zero<<<(K * D + 255) / 256, 256>>>();
    vq_prep<<<(K + 255) / 256, 256>>>(weight);
    vq_main<<<B_TOTAL / M_CTA, NT, SM_TOTAL>>>(z, weight, out + OFF_ZQ, out + OFF_IDX);
    vq_finalA<<<1, K>>>(ema_cs, out);
    vq_finalB<<<(K * D + 255) / 256, 256>>>(ema_es, ema_cs, out);
}

// round 10
// speedup vs baseline: 4.2759x; 1.1836x over previous
#include <cuda_runtime.h>
#include <cuda_fp16.h>
#include <cstdint>

// ---------------- problem constants ----------------
#define B_TOTAL 262144
#define D 64
#define K 1024
#define M_CTA 256            // rows per CTA
#define NT 256               // threads per CTA
#define TH 0.10f
#define BIAS 128.0f          // score bias: keeps all scores strictly positive

// Output layout (float32, reference return order)
#define OFF_ZQ    0
#define OFF_IDX   16777216            // B*D
#define OFF_LOSS  17039360            // + B
#define OFF_CS    17039361            // + 1
#define OFF_ES    17040385            // + K
#define OFF_W     17105921            // + K*D

// ---------------- device scratch (no cudaMalloc allowed) ----------------
__device__ float          g_wsq[K];      // BIAS - 0.5*||w||^2
__device__ unsigned int   g_counts[K];
__device__ float          g_embed[K * D];
__device__ float          g_loss;
__device__ float          g_n;
__device__ __half         g_wh[K * D];   // fp16 codebook

// ---------------- dynamic smem layout (bytes) ----------------
#define SM_SH   0          // 128 x 144B: z staging (fp16), then codebook tile buf0
#define SM_SL   18432      // 128 x 144B: codebook tile buf1
#define SM_W2   36864      // 1024 f32
#define SM_HIST 40960      // 1024 u32
#define SM_CI   45056      // uint2 [256][4] packed top-2
#define SM_TOTAL 53248

__device__ __forceinline__ void red_add_v4(float* p, float4 v) {
    asm volatile("red.global.add.v4.f32 [%0], {%1,%2,%3,%4};"
                 :: "l"(p), "f"(v.x), "f"(v.y), "f"(v.z), "f"(v.w) : "memory");
}

__device__ __forceinline__ void mma16816(float c[4], const uint32_t a[4],
                                         uint32_t b0, uint32_t b1) {
    asm volatile("mma.sync.aligned.m16n8k16.row.col.f32.f16.f16.f32 "
                 "{%0,%1,%2,%3}, {%4,%5,%6,%7}, {%8,%9}, {%0,%1,%2,%3};"
                 : "+f"(c[0]), "+f"(c[1]), "+f"(c[2]), "+f"(c[3])
                 : "r"(a[0]), "r"(a[1]), "r"(a[2]), "r"(a[3]), "r"(b0), "r"(b1));
}

__device__ __forceinline__ void ldmx4(uint32_t r[4], uint32_t saddr) {
    asm volatile("ldmatrix.sync.aligned.m8n8.x4.shared.b16 {%0,%1,%2,%3}, [%4];"
                 : "=r"(r[0]), "=r"(r[1]), "=r"(r[2]), "=r"(r[3]) : "r"(saddr));
}

__device__ __forceinline__ void cpasync16(uint32_t dst, const void* src) {
    asm volatile("cp.async.ca.shared.global [%0], [%1], 16;"
                 :: "r"(dst), "l"(src) : "memory");
}

// scores are strictly positive -> float bits order as unsigned ints
__device__ __forceinline__ uint32_t packsc(float s, int col) {
    return (__float_as_uint(s) & 0xFFFFFC00u) | (uint32_t)col;
}
__device__ __forceinline__ void unpacksc(uint32_t pk, float& s, int& col) {
    col = (int)(pk & 1023u);
    s = __uint_as_float(pk & 0xFFFFFC00u);
}

// ---------------- zero scratch ----------------
__global__ void vq_zero() {
    int i = blockIdx.x * blockDim.x + threadIdx.x;
    if (i < K * D) g_embed[i] = 0.0f;
    if (i < K)     g_counts[i] = 0u;
    if (i == 0)    g_loss = 0.0f;
}

// ---------------- prep: fp16 codebook + (BIAS - 0.5*w2) ----------------
__global__ void vq_prep(const float* __restrict__ weight) {
    int k = blockIdx.x * blockDim.x + threadIdx.x;
    if (k >= K) return;
    const float4* wp = (const float4*)(weight + (size_t)k * D);
    float s = 0.0f;
    for (int j = 0; j < D / 4; j++) {
        float4 v = wp[j];
        s = fmaf(v.x, v.x, s); s = fmaf(v.y, v.y, s);
        s = fmaf(v.z, v.z, s); s = fmaf(v.w, v.w, s);
        __half2 p0 = __floats2half2_rn(v.x, v.y);
        __half2 p1 = __floats2half2_rn(v.z, v.w);
        uint2 H = make_uint2(*(uint32_t*)&p0, *(uint32_t*)&p1);
        ((uint2*)(g_wh + (size_t)k * D))[j] = H;
    }
    g_wsq[k] = BIAS - 0.5f * s;
}

// ---------------- main fused kernel ----------------
__global__ __launch_bounds__(NT, 2)
void vq_main(const float* __restrict__ z,
             const float* __restrict__ weight,
             float* __restrict__ out_zq,
             float* __restrict__ out_idx) {
    extern __shared__ char sm[];
    const uint32_t smu = (uint32_t)__cvta_generic_to_shared(sm);
    const int tid  = threadIdx.x;
    const int wid  = tid >> 5;
    const int lane = tid & 31;
    const int wrb  = wid * 32;
    const int row0 = blockIdx.x * M_CTA;

    char*         sH    = sm + SM_SH;
    float*        sW2n  = (float*)(sm + SM_W2);
    unsigned int* sHist = (unsigned int*)(sm + SM_HIST);
    uint2*        sCI   = (uint2*)(sm + SM_CI);

    for (int i = tid; i < K; i += NT) { sW2n[i] = g_wsq[i]; sHist[i] = 0u; }

    // ---- phase 1: stage z (two halves of 128 rows) as fp16, build A fragments ----
    uint32_t aH[2][4][4];
    const int sr = tid >> 1;
    const int sc = (tid & 1) * 32;
#pragma unroll 1
    for (int h = 0; h < 2; h++) {
        __syncthreads();
        {
            const float4* zp = (const float4*)(z + ((size_t)(row0 + h * 128 + sr)) * D + sc);
            uint2* dH = (uint2*)(sH + sr * 144 + sc * 2);
#pragma unroll
            for (int j = 0; j < 8; j++) {
                float4 v = zp[j];
                __half2 p0 = __floats2half2_rn(v.x, v.y);
                __half2 p1 = __floats2half2_rn(v.z, v.w);
                dH[j] = make_uint2(*(uint32_t*)&p0, *(uint32_t*)&p1);
            }
        }
        __syncthreads();
        if ((wid >> 2) == h) {
            const int br = (wid & 3) * 32;
#pragma unroll
            for (int f = 0; f < 2; f++)
#pragma unroll
            for (int kk = 0; kk < 4; kk++) {
                int rr = br + f * 16 + (lane >> 2);
                int cb = (kk * 16 + (lane & 3) * 2) * 2;
                aH[f][kk][0] = *(const uint32_t*)(sH + rr * 144 + cb);
                aH[f][kk][1] = *(const uint32_t*)(sH + (rr + 8) * 144 + cb);
                aH[f][kk][2] = *(const uint32_t*)(sH + rr * 144 + cb + 16);
                aH[f][kk][3] = *(const uint32_t*)(sH + (rr + 8) * 144 + cb + 16);
            }
        }
    }
    __syncthreads();   // all frag reads done; sH/sL become codebook tile buffers

    // prefetch codebook tile 0 -> buf0 (sH)
    {
        const __half* src = g_wh + (size_t)sr * D + sc;
        uint32_t dst = smu + SM_SH + sr * 144 + sc * 2;
#pragma unroll
        for (int j = 0; j < 4; j++) cpasync16(dst + j * 16, src + j * 8);
        asm volatile("cp.async.commit_group;" ::: "memory");
    }

    // ldmatrix B addressing
    const uint32_t lmB = (uint32_t)((lane & 7) * 144 + (lane >> 3) * 16);

    // ---- phase 2: stream codebook tiles, single fp16 HMMA pass, packed top-2 ----
    uint32_t pk1[4], pk2[4];
#pragma unroll
    for (int s = 0; s < 4; s++) { pk1[s] = 0u; pk2[s] = 0u; }

#pragma unroll 1
    for (int t = 0; t < K / 128; t++) {
        if (t < 7) {
            const __half* src = g_wh + ((size_t)(t + 1) * 128 + sr) * D + sc;
            uint32_t dst = smu + ((t + 1) & 1 ? SM_SL : SM_SH) + sr * 144 + sc * 2;
#pragma unroll
            for (int j = 0; j < 4; j++) cpasync16(dst + j * 16, src + j * 8);
            asm volatile("cp.async.commit_group;" ::: "memory");
            asm volatile("cp.async.wait_group 1;" ::: "memory");
        } else {
            asm volatile("cp.async.wait_group 0;" ::: "memory");
        }
        __syncthreads();

        const uint32_t tbase = smu + ((t & 1) ? SM_SL : SM_SH);
#pragma unroll 1
        for (int nb = 0; nb < 16; nb++) {
            const int colb = t * 128 + nb * 8 + (lane & 3) * 2;
            float2 w2 = *(const float2*)&sW2n[colb];

            uint32_t bh[8];
            {
                uint32_t base = tbase + (uint32_t)(nb * 8) * 144u + lmB;
                ldmx4(bh,     base);
                ldmx4(bh + 4, base + 64);
            }

            // single fp16 pass, accumulators init'd with biased -0.5*w2
            float c0[4] = {w2.x, w2.y, w2.x, w2.y};
            float c1[4] = {w2.x, w2.y, w2.x, w2.y};

#pragma unroll
            for (int kk = 0; kk < 4; kk++) {
                mma16816(c0, aH[0][kk], bh[2 * kk], bh[2 * kk + 1]);
                mma16816(c1, aH[1][kk], bh[2 * kk], bh[2 * kk + 1]);
            }

            // branch-free FULL top-2 on packed positive-float bits
#define TOP2(s, va, vb) do {                                                  \
                uint32_t _p0 = packsc(va, colb);                              \
                uint32_t _p1 = packsc(vb, colb + 1);                          \
                uint32_t _m1 = max(_p0, _p1), _m2 = min(_p0, _p1);            \
                pk2[s] = max(pk2[s], max(min(pk1[s], _m1), _m2));             \
                pk1[s] = max(pk1[s], _m1);                                    \
            } while (0)
            TOP2(0, c0[0], c0[1]);
            TOP2(1, c0[2], c0[3]);
            TOP2(2, c1[0], c1[1]);
            TOP2(3, c1[2], c1[3]);
#undef TOP2
        }
        __syncthreads();   // all warps done with buf[t&1] before it is re-prefetched
    }

    // ---- write per-lane packed candidates (8 per row) ----
#pragma unroll
    for (int s = 0; s < 4; s++) {
        int rl = wrb + (lane >> 2) + 8 * s;
        sCI[rl * 4 + (lane & 3)] = make_uint2(pk1[s], pk2[s]);
    }
    __syncthreads();

    // ---- epilogue: exact fp32 re-check of candidates near the approx best ----
    {
        const int row = row0 + tid;
        float scv[8]; int idv[8];
#pragma unroll
        for (int q = 0; q < 4; q++) {
            uint2 c = sCI[tid * 4 + q];
            unpacksc(c.x, scv[2 * q],     idv[2 * q]);
            unpacksc(c.y, scv[2 * q + 1], idv[2 * q + 1]);
        }
        float bs = scv[0];
#pragma unroll
        for (int q = 1; q < 8; q++) bs = fmaxf(bs, scv[q]);

        float4 zr[D / 4];
        const float4* zp = (const float4*)(z + (size_t)row * D);
#pragma unroll
        for (int j = 0; j < D / 4; j++) zr[j] = zp[j];

        float bd2 = 3.4e38f; int bidx = K;
#pragma unroll 1
        for (int q = 0; q < 8; q++) {
            if (scv[q] >= bs - TH) {
                const float4* wv = (const float4*)(weight + (size_t)idv[q] * D);
                float d2 = 0.0f;
#pragma unroll
                for (int j = 0; j < D / 4; j++) {
                    float4 w = wv[j];
                    float dx = zr[j].x - w.x, dy = zr[j].y - w.y;
                    float dz = zr[j].z - w.z, dw = zr[j].w - w.w;
                    d2 = fmaf(dx, dx, d2); d2 = fmaf(dy, dy, d2);
                    d2 = fmaf(dz, dz, d2); d2 = fmaf(dw, dw, d2);
                }
                if (d2 < bd2 || (d2 == bd2 && idv[q] < bidx)) { bd2 = d2; bidx = idv[q]; }
            }
        }

        const float4* wv = (const float4*)(weight + (size_t)bidx * D);
        float4* op = (float4*)(out_zq + (size_t)row * D);
        float* eb = g_embed + (size_t)bidx * D;
#pragma unroll
        for (int j = 0; j < D / 4; j++) {
            op[j] = wv[j];
            red_add_v4(eb + 4 * j, zr[j]);
        }
        out_idx[row] = (float)bidx;
        atomicAdd(&sHist[bidx], 1u);

        float d2 = bd2;
#pragma unroll
        for (int o = 16; o; o >>= 1) d2 += __shfl_xor_sync(0xffffffffu, d2, o);
        if (lane == 0) atomicAdd(&g_loss, d2);
    }
    __syncthreads();
    for (int i = tid; i < K; i += NT) {
        unsigned int c = sHist[i];
        if (c) atomicAdd(&g_counts[i], c);
    }
}

// ---------------- finalize ----------------
__global__ void vq_finalA(const float* __restrict__ ema_cs, float* __restrict__ out) {
    __shared__ float sSum[K];
    int k = threadIdx.x;
    float ncs = fmaf(0.99f, ema_cs[k], 0.01f * (float)g_counts[k]);
    out[OFF_CS + k] = ncs;
    sSum[k] = ncs;
    __syncthreads();
#pragma unroll
    for (int s = K / 2; s > 0; s >>= 1) {
        if (k < s) sSum[k] += sSum[k + s];
        __syncthreads();
    }
    if (k == 0) {
        g_n = sSum[0];
        out[OFF_LOSS] = 0.25f * g_loss / (float)(B_TOTAL * D);
    }
}

__global__ void vq_finalB(const float* __restrict__ ema_es,
                          const float* __restrict__ ema_cs,
                          float* __restrict__ out) {
    int i = blockIdx.x * blockDim.x + threadIdx.x;
    if (i >= K * D) return;
    int k = i >> 6;
    float nes = fmaf(0.99f, ema_es[i], 0.01f * g_embed[i]);
    out[OFF_ES + i] = nes;
    float ncs = fmaf(0.99f, ema_cs[k], 0.01f * (float)g_counts[k]);
    float n = g_n;
    float smoothed = (ncs + 1e-5f) / (n + (float)K * 1e-5f) * n;
    out[OFF_W + i] = nes / smoothed;
}

extern "C" void kernel_launch(void* const* d_in, const int* in_sizes, int n_in,
                              void* d_out, int out_size) {
    const float* z      = (const float*)d_in[0];
    const float* weight = (const float*)d_in[1];
    const float* ema_cs = (const float*)d_in[2];
    const float* ema_es = (const float*)d_in[3];
    float* out = (float*)d_out;

    cudaFuncSetAttribute(vq_main, cudaFuncAttributeMaxDynamicSharedMemorySize, SM_TOTAL);

    vq_zero<<<(K * D + 255) / 256, 256>>>();
    vq_prep<<<(K + 255) / 256, 256>>>(weight);
    vq_main<<<B_TOTAL / M_CTA, NT, SM_TOTAL>>>(z, weight, out + OFF_ZQ, out + OFF_IDX);
    vq_finalA<<<1, K>>>(ema_cs, out);
    vq_finalB<<<(K * D + 255) / 256, 256>>>(ema_es, ema_cs, out);
}